// round 15
// baseline (speedup 1.0000x reference)
#include <cuda_runtime.h>
#include <cuda_fp16.h>
#include <stdint.h>

// ============================================================================
// B=1024, F=64, D=64.
//   layer: h'[o,d] = relu(b[o] + sum_{i,j} W[o,i*64+j] * x[i,d] * h[j,d])
//   out[b] = bfc + sum_o Wfc[o]*sum_d h1 + sum_o Wfc[64+o]*sum_d h2
//
// x-folded h-stationary HMMA (mma.sync m16n8k16 f16->f32):
//   acc += W_i @ (h * x[i,:])    -- x folded into the B operand, MMAs
//   accumulate directly into acc (no G buffer, no FFMA drain).
// R15 deltas vs R14 (191us, tensor 57.5%):
//   1. x pre-splatted to packed fp16 pairs in smem at init -> chunk loop has
//      one LDS.32 per np, no CVT (same numerics: fp16(x) rounding unchanged).
//   2. zb double-buffered one kk ahead: zb[(kk+1)&1] computed AFTER issuing
//      kk's MMAs (static indices inside the unrolled kk loop, same pattern as
//      the A[kk&1] buffer) -> HMUL2->MMA RAW gap grows to ~8 MMA issues.
// Single fp16 W and h (rel_err 1.49e-4 measured, ~6.7x margin).
// Bh persistent in registers per layer. W pre-arranged in mma-A fragment
// order, coalesced LDG.128 double-buffered. 128 thr (2mh x 2nh, m32n32),
// regs ~122 -> 4 CTAs/SM.
// ============================================================================

#define HH_OFF   0            // h fp16 [j*144B], 64 rows = 9216
#define XP_OFF   9216         // x splat fp16x2 [i*68 + d] uint32 = 17408
#define POOL_OFF 26624
#define SMEM_TOTAL 26688

// W in fragment order: index ((c*2 + mh)*8 + q)*32 + lane, q = kk*2 + m
__device__ __align__(16) uint4 g_Wf[65536];   // 1 MB

// ---------------------------------------------------------------------------
static __device__ __forceinline__ uint32_t s2u(const void* p) {
    uint32_t a;
    asm("{ .reg .u64 t; cvta.to.shared.u64 t, %1; cvt.u32.u64 %0, t; }"
        : "=r"(a) : "l"(p));
    return a;
}
static __device__ __forceinline__ uint32_t h2bits(__half2 h) {
    return *reinterpret_cast<uint32_t*>(&h);
}

#define LDSM4T(r, addr) \
    asm volatile("ldmatrix.sync.aligned.m8n8.x4.trans.shared.b16 {%0,%1,%2,%3}, [%4];" \
                 : "=r"((r)[0]), "=r"((r)[1]), "=r"((r)[2]), "=r"((r)[3]) \
                 : "r"(addr))
#define MMAH(c, a, b0, b1) \
    asm volatile("mma.sync.aligned.m16n8k16.row.col.f32.f16.f16.f32 " \
                 "{%0,%1,%2,%3},{%4,%5,%6,%7},{%8,%9},{%0,%1,%2,%3};" \
                 : "+f"((c)[0]), "+f"((c)[1]), "+f"((c)[2]), "+f"((c)[3]) \
                 : "r"((a)[0]), "r"((a)[1]), "r"((a)[2]), "r"((a)[3]), \
                   "r"(b0), "r"(b1))
#define MMAHZ(c, a, b0, b1) \
    asm volatile("mma.sync.aligned.m16n8k16.row.col.f32.f16.f16.f32 " \
                 "{%0,%1,%2,%3},{%4,%5,%6,%7},{%8,%9},{%10,%10,%10,%10};" \
                 : "=f"((c)[0]), "=f"((c)[1]), "=f"((c)[2]), "=f"((c)[3]) \
                 : "r"((a)[0]), "r"((a)[1]), "r"((a)[2]), "r"((a)[3]), \
                   "r"(b0), "r"(b1), "f"(0.0f))
#define HMUL2(d, a, b) \
    asm("mul.rn.f16x2 %0, %1, %2;" : "=r"(d) : "r"(a), "r"(b))

// ---------------------------------------------------------------------------
// Prologue: W -> fp16 in mma-A fragment order.
__global__ void CIN_52553219834054_wsplit(const float* __restrict__ W1,
                                          const float* __restrict__ W2) {
    const int idx = blockIdx.x * 256 + threadIdx.x;    // 0..65535
    const int c    = idx >> 9;
    const int rem  = idx & 511;
    const int mh   = rem >> 8;
    const int rem2 = rem & 255;
    const int q    = rem2 >> 5;
    const int lane = rem2 & 31;
    const int kk = q >> 1, m = q & 1;
    const int l = c >> 6, i = c & 63;
    const float* __restrict__ W = l ? W2 : W1;
    const int r = lane >> 2, tg = lane & 3;

    uint32_t regs[4];
    #pragma unroll
    for (int e = 0; e < 4; ++e) {
        const int row = mh * 32 + m * 16 + r + (e & 1) * 8;
        const int j   = kk * 16 + tg * 2 + (e >> 1) * 8;
        const float v0 = W[row * 4096 + i * 64 + j];
        const float v1 = W[row * 4096 + i * 64 + j + 1];
        regs[e] = h2bits(__floats2half2_rn(v0, v1));   // .x = v0 (low bits)
    }
    g_Wf[idx] = make_uint4(regs[0], regs[1], regs[2], regs[3]);
}

// ---------------------------------------------------------------------------
__global__ __launch_bounds__(128, 4) void CIN_52553219834054_kernel(
    const float* __restrict__ x,
    const float* __restrict__ b1, const float* __restrict__ b2,
    const float* __restrict__ Wfc, const float* __restrict__ bfc,
    float* __restrict__ out)
{
    extern __shared__ __align__(16) char smem[];
    const uint32_t sb = s2u(smem);
    const int tid = threadIdx.x, wid = tid >> 5, lane = tid & 31;
    const int mh = wid >> 1;          // m-half (rows mh*32..+31)
    const int nh = wid & 1;           // n-half (cols nh*32..+31)

    // ---- init: x -> XP fp16 splat pairs; h0 = fp16(x) ----
    {
        const float4* xg = (const float4*)(x + (size_t)blockIdx.x * 4096);
        uint32_t* XP = (uint32_t*)(smem + XP_OFF);
        char* hb = smem + HH_OFF;
        #pragma unroll
        for (int t = 0; t < 8; ++t) {
            const int q = tid + t * 128;            // 0..1023
            const int i = q >> 4, d4 = (q & 15) * 4;
            const float4 v = xg[q];
            XP[i * 68 + d4 + 0] = h2bits(__floats2half2_rn(v.x, v.x));
            XP[i * 68 + d4 + 1] = h2bits(__floats2half2_rn(v.y, v.y));
            XP[i * 68 + d4 + 2] = h2bits(__floats2half2_rn(v.z, v.z));
            XP[i * 68 + d4 + 3] = h2bits(__floats2half2_rn(v.w, v.w));
            *(uint2*)(hb + i * 144 + d4 * 2) =
                make_uint2(h2bits(__floats2half2_rn(v.x, v.y)),
                           h2bits(__floats2half2_rn(v.z, v.w)));
        }
    }
    __syncthreads();

    // h LDSM base for this warp: + kk*2304 + g*32
    const uint32_t hbase = sb + HH_OFF + (lane & 15) * 144
                         + ((lane >> 4) << 4) + (nh * 2) * 32;
    const uint4* __restrict__ wfp = &g_Wf[mh * 256 + lane];  // + c*512 + kk*64
    // x splat pointer: lane's d values are nh*32 + np*8 + (lane>>2)
    const uint32_t* __restrict__ xpc = (const uint32_t*)(smem + XP_OFF)
                                     + nh * 32 + (lane >> 2);

    // A-fragment double buffer: [buf][m]
    uint4 A[2][2];
    {   // preload chunk 0, kk 0
        A[0][0] = __ldg(wfp); A[0][1] = __ldg(wfp + 32);
    }

    float pool = 0.0f;

    #pragma unroll 1
    for (int l = 0; l < 2; ++l) {
        // ---- h B-fragments (fp16) into registers, once per layer ----
        uint32_t Bh[4][2][4];
        {
            #pragma unroll
            for (int kk = 0; kk < 4; ++kk)
                #pragma unroll
                for (int g = 0; g < 2; ++g)
                    LDSM4T(Bh[kk][g], hbase + kk * 2304 + g * 32);
        }
        __syncthreads();   // all B-frags read before epilogue may rewrite h

        float acc[2][4][4];

        #pragma unroll 1
        for (int i = 0; i < 64; ++i) {
            const int c = l * 64 + i;

            // x splats for this chunk: one LDS.32 per np
            uint32_t xs2[4];
            #pragma unroll
            for (int np = 0; np < 4; ++np)
                xs2[np] = xpc[i * 68 + np * 8];

            // zb double buffer, one kk ahead (static indices, kk unrolled)
            uint32_t zb[2][4][2];
            #pragma unroll
            for (int np = 0; np < 4; ++np) {
                const int g = np >> 1, pr = (np & 1) * 2;
                HMUL2(zb[0][np][0], Bh[0][g][pr],     xs2[np]);
                HMUL2(zb[0][np][1], Bh[0][g][pr + 1], xs2[np]);
            }

            #pragma unroll
            for (int kk = 0; kk < 4; ++kk) {
                // prefetch next (chunk, kk) A-fragments
                {
                    const int nkk = (kk + 1) & 3;
                    const int nc  = (kk == 3) ? c + 1 : c;
                    if (nc < 128) {
                        const uint4* p = wfp + nc * 512 + nkk * 64;
                        uint4* dst = A[(kk + 1) & 1];
                        dst[0] = __ldg(p); dst[1] = __ldg(p + 32);
                    }
                }
                const uint32_t* Ah[2] = { (const uint32_t*)&A[kk & 1][0],
                                          (const uint32_t*)&A[kk & 1][1] };
                const uint32_t (*zc)[2] = zb[kk & 1];
                #pragma unroll
                for (int m = 0; m < 2; ++m)
                    #pragma unroll
                    for (int np = 0; np < 4; ++np) {
                        if (i == 0 && kk == 0) {
                            MMAHZ(acc[m][np], Ah[m], zc[np][0], zc[np][1]);
                        } else {
                            MMAH (acc[m][np], Ah[m], zc[np][0], zc[np][1]);
                        }
                    }
                // compute zb for next kk AFTER issuing this kk's MMAs
                if (kk < 3) {
                    #pragma unroll
                    for (int np = 0; np < 4; ++np) {
                        const int g = np >> 1, pr = (np & 1) * 2;
                        HMUL2(zb[(kk + 1) & 1][np][0],
                              Bh[kk + 1][g][pr],     xs2[np]);
                        HMUL2(zb[(kk + 1) & 1][np][1],
                              Bh[kk + 1][g][pr + 1], xs2[np]);
                    }
                }
            }
        }
        __syncthreads();   // all h reads done before epilogue rewrites h

        // ---- epilogue: bias + relu, pool, write next h (fp16) ----
        {
            const float* bg = l ? b2 : b1;
            const int d0 = nh * 32 + (lane & 3) * 2;
            char* hb = smem + HH_OFF;
            float ps = 0.0f;
            #pragma unroll
            for (int m = 0; m < 2; ++m) {
                const int o_lo = mh * 32 + m * 16 + (lane >> 2);
                const int o_hi = o_lo + 8;
                const float blv = bg[o_lo], bhv = bg[o_hi];
                const float wlv = Wfc[l * 64 + o_lo], whv = Wfc[l * 64 + o_hi];
                #pragma unroll
                for (int np = 0; np < 4; ++np) {
                    const int d = d0 + np * 8;
                    float v0 = fmaxf(acc[m][np][0] + blv, 0.0f);
                    float v1 = fmaxf(acc[m][np][1] + blv, 0.0f);
                    float v2 = fmaxf(acc[m][np][2] + bhv, 0.0f);
                    float v3 = fmaxf(acc[m][np][3] + bhv, 0.0f);
                    ps += wlv * (v0 + v1) + whv * (v2 + v3);
                    if (l == 0) {
                        *(uint32_t*)(hb + o_lo * 144 + d * 2) =
                            h2bits(__floats2half2_rn(v0, v1));
                        *(uint32_t*)(hb + o_hi * 144 + d * 2) =
                            h2bits(__floats2half2_rn(v2, v3));
                    }
                }
            }
            pool += ps;
        }
        __syncthreads();   // new h visible before next-layer Bh load
    }

    // ---- reduce pool across 4 warps, write out ----
    #pragma unroll
    for (int off = 16; off > 0; off >>= 1)
        pool += __shfl_xor_sync(0xffffffffu, pool, off);
    float* pb = (float*)(smem + POOL_OFF);
    if (lane == 0) pb[wid] = pool;
    __syncthreads();
    if (tid == 0)
        out[blockIdx.x] = pb[0] + pb[1] + pb[2] + pb[3] + bfc[0];
}

// ---------------------------------------------------------------------------
extern "C" void kernel_launch(void* const* d_in, const int* in_sizes, int n_in,
                              void* d_out, int out_size) {
    const float* x   = (const float*)d_in[0];
    const float* W1  = (const float*)d_in[1];
    const float* b1  = (const float*)d_in[2];
    const float* W2  = (const float*)d_in[3];
    const float* b2  = (const float*)d_in[4];
    const float* Wfc = (const float*)d_in[5];
    const float* bfc = (const float*)d_in[6];

    cudaFuncSetAttribute(CIN_52553219834054_kernel,
                         cudaFuncAttributeMaxDynamicSharedMemorySize, SMEM_TOTAL);

    CIN_52553219834054_wsplit<<<256, 256>>>(W1, W2);
    CIN_52553219834054_kernel<<<1024, 128, SMEM_TOTAL>>>(
        x, b1, b2, Wfc, bfc, (float*)d_out);
}

// round 16
// speedup vs baseline: 1.0989x; 1.0989x over previous
#include <cuda_runtime.h>
#include <cuda_fp16.h>
#include <stdint.h>

// ============================================================================
// B=1024, F=64, D=64.
//   layer: h'[o,d] = relu(b[o] + sum_{i,j} W[o,i*64+j] * x[i,d] * h[j,d])
//   out[b] = bfc + sum_o Wfc[o]*sum_d h1 + sum_o Wfc[64+o]*sum_d h2
//
// x-folded h-stationary HMMA (mma.sync m16n8k16 f16->f32):
//   acc += W_i @ (h * x[i,:])   -- x folded into B via one mul.rn.f16x2 per
//   frag reg; MMAs accumulate directly into acc (no G buffer).
// R16 delta vs R14 (191us, tensor 57.5%): A-fragment prefetch distance
// doubled. 4-slot ring A[4][2]: consume A[kk], prefetch global step s+2 into
// A[(kk+2)&3]. Chunks are 4-aligned so s&3 == kk -> all indices compile-time
// (R12 lesson: runtime-indexed arrays => local memory). Distance ~16 MMA
// issues (~128+ cyc) now covers L1 (39) and most L2 (234) excursions; the
// old 1-step distance (~64 cyc) left every L1 miss as a full MMA-stream
// stall. (R15 lesson: the HMUL2->MMA chain was NOT the stall - reverted.)
// Single fp16 W and h (rel_err 1.49e-4, ~6.7x margin). Bh persistent in regs
// per layer. 128 thr (2mh x 2nh, m32n32), regs ~126 -> 4 CTAs/SM.
// ============================================================================

#define HH_OFF   0            // h fp16 [j*144B], 64 rows = 9216
#define XS_OFF   9216         // x fp32 [i*68 + d] = 17408
#define POOL_OFF 26624
#define SMEM_TOTAL 26688

// W in fragment order: index ((c*2 + mh)*8 + q)*32 + lane, q = kk*2 + m
__device__ __align__(16) uint4 g_Wf[65536];   // 1 MB

// ---------------------------------------------------------------------------
static __device__ __forceinline__ uint32_t s2u(const void* p) {
    uint32_t a;
    asm("{ .reg .u64 t; cvta.to.shared.u64 t, %1; cvt.u32.u64 %0, t; }"
        : "=r"(a) : "l"(p));
    return a;
}
static __device__ __forceinline__ uint32_t h2bits(__half2 h) {
    return *reinterpret_cast<uint32_t*>(&h);
}

#define LDSM4T(r, addr) \
    asm volatile("ldmatrix.sync.aligned.m8n8.x4.trans.shared.b16 {%0,%1,%2,%3}, [%4];" \
                 : "=r"((r)[0]), "=r"((r)[1]), "=r"((r)[2]), "=r"((r)[3]) \
                 : "r"(addr))
#define MMAH(c, a, b0, b1) \
    asm volatile("mma.sync.aligned.m16n8k16.row.col.f32.f16.f16.f32 " \
                 "{%0,%1,%2,%3},{%4,%5,%6,%7},{%8,%9},{%0,%1,%2,%3};" \
                 : "+f"((c)[0]), "+f"((c)[1]), "+f"((c)[2]), "+f"((c)[3]) \
                 : "r"((a)[0]), "r"((a)[1]), "r"((a)[2]), "r"((a)[3]), \
                   "r"(b0), "r"(b1))
#define MMAHZ(c, a, b0, b1) \
    asm volatile("mma.sync.aligned.m16n8k16.row.col.f32.f16.f16.f32 " \
                 "{%0,%1,%2,%3},{%4,%5,%6,%7},{%8,%9},{%10,%10,%10,%10};" \
                 : "=f"((c)[0]), "=f"((c)[1]), "=f"((c)[2]), "=f"((c)[3]) \
                 : "r"((a)[0]), "r"((a)[1]), "r"((a)[2]), "r"((a)[3]), \
                   "r"(b0), "r"(b1), "f"(0.0f))
#define HMUL2(d, a, b) \
    asm("mul.rn.f16x2 %0, %1, %2;" : "=r"(d) : "r"(a), "r"(b))
#define SPLATH2(d, f) \
    asm("cvt.rn.f16x2.f32 %0, %1, %1;" : "=r"(d) : "f"(f))

// ---------------------------------------------------------------------------
// Prologue: W -> fp16 in mma-A fragment order.
__global__ void CIN_52553219834054_wsplit(const float* __restrict__ W1,
                                          const float* __restrict__ W2) {
    const int idx = blockIdx.x * 256 + threadIdx.x;    // 0..65535
    const int c    = idx >> 9;
    const int rem  = idx & 511;
    const int mh   = rem >> 8;
    const int rem2 = rem & 255;
    const int q    = rem2 >> 5;
    const int lane = rem2 & 31;
    const int kk = q >> 1, m = q & 1;
    const int l = c >> 6, i = c & 63;
    const float* __restrict__ W = l ? W2 : W1;
    const int r = lane >> 2, tg = lane & 3;

    uint32_t regs[4];
    #pragma unroll
    for (int e = 0; e < 4; ++e) {
        const int row = mh * 32 + m * 16 + r + (e & 1) * 8;
        const int j   = kk * 16 + tg * 2 + (e >> 1) * 8;
        const float v0 = W[row * 4096 + i * 64 + j];
        const float v1 = W[row * 4096 + i * 64 + j + 1];
        regs[e] = h2bits(__floats2half2_rn(v0, v1));   // .x = v0 (low bits)
    }
    g_Wf[idx] = make_uint4(regs[0], regs[1], regs[2], regs[3]);
}

// ---------------------------------------------------------------------------
__global__ __launch_bounds__(128, 4) void CIN_52553219834054_kernel(
    const float* __restrict__ x,
    const float* __restrict__ b1, const float* __restrict__ b2,
    const float* __restrict__ Wfc, const float* __restrict__ bfc,
    float* __restrict__ out)
{
    extern __shared__ __align__(16) char smem[];
    const uint32_t sb = s2u(smem);
    const int tid = threadIdx.x, wid = tid >> 5, lane = tid & 31;
    const int mh = wid >> 1;          // m-half (rows mh*32..+31)
    const int nh = wid & 1;           // n-half (cols nh*32..+31)

    // ---- init: x -> XS fp32; h0 = fp16(x) ----
    {
        const float4* xg = (const float4*)(x + (size_t)blockIdx.x * 4096);
        float* XSf = (float*)(smem + XS_OFF);
        char* hb = smem + HH_OFF;
        #pragma unroll
        for (int t = 0; t < 8; ++t) {
            const int q = tid + t * 128;            // 0..1023
            const int i = q >> 4, d4 = (q & 15) * 4;
            const float4 v = xg[q];
            *(float4*)(XSf + i * 68 + d4) = v;
            *(uint2*)(hb + i * 144 + d4 * 2) =
                make_uint2(h2bits(__floats2half2_rn(v.x, v.y)),
                           h2bits(__floats2half2_rn(v.z, v.w)));
        }
    }
    __syncthreads();

    // h LDSM base for this warp: + kk*2304 + g*32
    const uint32_t hbase = sb + HH_OFF + (lane & 15) * 144
                         + ((lane >> 4) << 4) + (nh * 2) * 32;
    const uint4* __restrict__ wfp = &g_Wf[mh * 256 + lane];  // + c*512 + kk*64
    // x for the B-frag scaling: lane's d values are nh*32 + np*8 + (lane>>2)
    const float* __restrict__ xcol = (const float*)(smem + XS_OFF)
                                   + nh * 32 + (lane >> 2);

    // A-fragment 4-slot ring: consume A[kk], prefetch step+2 into A[(kk+2)&3]
    uint4 A[4][2];
    {   // preload steps 0 and 1 (chunk 0, kk 0..1)
        A[0][0] = __ldg(wfp);      A[0][1] = __ldg(wfp + 32);
        A[1][0] = __ldg(wfp + 64); A[1][1] = __ldg(wfp + 96);
    }

    float pool = 0.0f;

    #pragma unroll 1
    for (int l = 0; l < 2; ++l) {
        // ---- h B-fragments (fp16) into registers, once per layer ----
        uint32_t Bh[4][2][4];
        {
            #pragma unroll
            for (int kk = 0; kk < 4; ++kk)
                #pragma unroll
                for (int g = 0; g < 2; ++g)
                    LDSM4T(Bh[kk][g], hbase + kk * 2304 + g * 32);
        }
        __syncthreads();   // all B-frags read before epilogue may rewrite h

        float acc[2][4][4];

        #pragma unroll 1
        for (int i = 0; i < 64; ++i) {
            const int c = l * 64 + i;

            // x splats for this chunk: one per np (d = nh*32 + np*8 + lane>>2)
            uint32_t xs2[4];
            #pragma unroll
            for (int np = 0; np < 4; ++np)
                SPLATH2(xs2[np], xcol[i * 68 + np * 8]);

            #pragma unroll
            for (int kk = 0; kk < 4; ++kk) {
                // prefetch A-fragments 2 steps ahead (s = c*4+kk; s&3 == kk)
                {
                    const int nc  = (kk >= 2) ? c + 1 : c;
                    const int nkk = (kk + 2) & 3;
                    if (nc < 128) {
                        const uint4* p = wfp + nc * 512 + nkk * 64;
                        uint4* dst = A[(kk + 2) & 3];
                        dst[0] = __ldg(p); dst[1] = __ldg(p + 32);
                    }
                }
                // scale B-frags by x (one f16x2 mul per reg)
                uint32_t zb[4][2];
                #pragma unroll
                for (int np = 0; np < 4; ++np) {
                    const int g = np >> 1, pr = (np & 1) * 2;
                    HMUL2(zb[np][0], Bh[kk][g][pr],     xs2[np]);
                    HMUL2(zb[np][1], Bh[kk][g][pr + 1], xs2[np]);
                }
                const uint32_t* Ah[2] = { (const uint32_t*)&A[kk][0],
                                          (const uint32_t*)&A[kk][1] };
                #pragma unroll
                for (int m = 0; m < 2; ++m)
                    #pragma unroll
                    for (int np = 0; np < 4; ++np) {
                        if (i == 0 && kk == 0) {
                            MMAHZ(acc[m][np], Ah[m], zb[np][0], zb[np][1]);
                        } else {
                            MMAH (acc[m][np], Ah[m], zb[np][0], zb[np][1]);
                        }
                    }
            }
        }
        __syncthreads();   // all h reads done before epilogue rewrites h

        // ---- epilogue: bias + relu, pool, write next h (fp16) ----
        {
            const float* bg = l ? b2 : b1;
            const int d0 = nh * 32 + (lane & 3) * 2;
            char* hb = smem + HH_OFF;
            float ps = 0.0f;
            #pragma unroll
            for (int m = 0; m < 2; ++m) {
                const int o_lo = mh * 32 + m * 16 + (lane >> 2);
                const int o_hi = o_lo + 8;
                const float blv = bg[o_lo], bhv = bg[o_hi];
                const float wlv = Wfc[l * 64 + o_lo], whv = Wfc[l * 64 + o_hi];
                #pragma unroll
                for (int np = 0; np < 4; ++np) {
                    const int d = d0 + np * 8;
                    float v0 = fmaxf(acc[m][np][0] + blv, 0.0f);
                    float v1 = fmaxf(acc[m][np][1] + blv, 0.0f);
                    float v2 = fmaxf(acc[m][np][2] + bhv, 0.0f);
                    float v3 = fmaxf(acc[m][np][3] + bhv, 0.0f);
                    ps += wlv * (v0 + v1) + whv * (v2 + v3);
                    if (l == 0) {
                        *(uint32_t*)(hb + o_lo * 144 + d * 2) =
                            h2bits(__floats2half2_rn(v0, v1));
                        *(uint32_t*)(hb + o_hi * 144 + d * 2) =
                            h2bits(__floats2half2_rn(v2, v3));
                    }
                }
            }
            pool += ps;
        }
        __syncthreads();   // new h visible before next-layer Bh load
    }

    // ---- reduce pool across 4 warps, write out ----
    #pragma unroll
    for (int off = 16; off > 0; off >>= 1)
        pool += __shfl_xor_sync(0xffffffffu, pool, off);
    float* pb = (float*)(smem + POOL_OFF);
    if (lane == 0) pb[wid] = pool;
    __syncthreads();
    if (tid == 0)
        out[blockIdx.x] = pb[0] + pb[1] + pb[2] + pb[3] + bfc[0];
}

// ---------------------------------------------------------------------------
extern "C" void kernel_launch(void* const* d_in, const int* in_sizes, int n_in,
                              void* d_out, int out_size) {
    const float* x   = (const float*)d_in[0];
    const float* W1  = (const float*)d_in[1];
    const float* b1  = (const float*)d_in[2];
    const float* W2  = (const float*)d_in[3];
    const float* b2  = (const float*)d_in[4];
    const float* Wfc = (const float*)d_in[5];
    const float* bfc = (const float*)d_in[6];

    cudaFuncSetAttribute(CIN_52553219834054_kernel,
                         cudaFuncAttributeMaxDynamicSharedMemorySize, SMEM_TOTAL);

    CIN_52553219834054_wsplit<<<256, 256>>>(W1, W2);
    CIN_52553219834054_kernel<<<1024, 128, SMEM_TOTAL>>>(
        x, b1, b2, Wfc, bfc, (float*)d_out);
}

// round 17
// speedup vs baseline: 1.1678x; 1.0627x over previous
#include <cuda_runtime.h>
#include <cuda_fp16.h>
#include <stdint.h>

// ============================================================================
// B=1024, F=64, D=64.
//   layer: h'[o,d] = relu(b[o] + sum_{i,j} W[o,i*64+j] * x[i,d] * h[j,d])
//   out[b] = bfc + sum_o Wfc[o]*sum_d h1 + sum_o Wfc[64+o]*sum_d h2
//
// x-folded h-stationary HMMA (mma.sync m16n8k16 f16->f32):
//   acc += W_i @ (h * x[i,:])   -- x folded into B via one mul.rn.f16x2 per
//   frag reg; MMAs accumulate directly into acc (no G buffer).
// R17 deltas vs R16 (182.8us, tensor 77.1%):
//   1. A-ring prefetch distance 2 -> 3 (consume A[kk], fetch s+3 into
//      A[(kk+3)&3]; all indices compile-time). ~24 MMA issues (~190+ cyc)
//      now covers far-die L2 (262) almost fully - kills residual
//      long-scoreboard stalls from 4-CTA/SM L1 thrash.
//   2. #pragma unroll 2 on the i-loop: ptxas software-pipelines the chunk
//      boundary, hoisting chunk i+1's xcol LDS + SPLATH2 chain into chunk
//      i's MMA shadow (removes the chunk-top serial window).
// Single fp16 W and h (rel_err 1.489e-4, ~6.7x margin). Bh persistent in
// regs per layer. 128 thr (2mh x 2nh, m32n32), regs ~125 -> 4 CTAs/SM.
// ============================================================================

#define HH_OFF   0            // h fp16 [j*144B], 64 rows = 9216
#define XS_OFF   9216         // x fp32 [i*68 + d] = 17408
#define POOL_OFF 26624
#define SMEM_TOTAL 26688

// W in fragment order: index ((c*2 + mh)*8 + q)*32 + lane, q = kk*2 + m
__device__ __align__(16) uint4 g_Wf[65536];   // 1 MB

// ---------------------------------------------------------------------------
static __device__ __forceinline__ uint32_t s2u(const void* p) {
    uint32_t a;
    asm("{ .reg .u64 t; cvta.to.shared.u64 t, %1; cvt.u32.u64 %0, t; }"
        : "=r"(a) : "l"(p));
    return a;
}
static __device__ __forceinline__ uint32_t h2bits(__half2 h) {
    return *reinterpret_cast<uint32_t*>(&h);
}

#define LDSM4T(r, addr) \
    asm volatile("ldmatrix.sync.aligned.m8n8.x4.trans.shared.b16 {%0,%1,%2,%3}, [%4];" \
                 : "=r"((r)[0]), "=r"((r)[1]), "=r"((r)[2]), "=r"((r)[3]) \
                 : "r"(addr))
#define MMAH(c, a, b0, b1) \
    asm volatile("mma.sync.aligned.m16n8k16.row.col.f32.f16.f16.f32 " \
                 "{%0,%1,%2,%3},{%4,%5,%6,%7},{%8,%9},{%0,%1,%2,%3};" \
                 : "+f"((c)[0]), "+f"((c)[1]), "+f"((c)[2]), "+f"((c)[3]) \
                 : "r"((a)[0]), "r"((a)[1]), "r"((a)[2]), "r"((a)[3]), \
                   "r"(b0), "r"(b1))
#define MMAHZ(c, a, b0, b1) \
    asm volatile("mma.sync.aligned.m16n8k16.row.col.f32.f16.f16.f32 " \
                 "{%0,%1,%2,%3},{%4,%5,%6,%7},{%8,%9},{%10,%10,%10,%10};" \
                 : "=f"((c)[0]), "=f"((c)[1]), "=f"((c)[2]), "=f"((c)[3]) \
                 : "r"((a)[0]), "r"((a)[1]), "r"((a)[2]), "r"((a)[3]), \
                   "r"(b0), "r"(b1), "f"(0.0f))
#define HMUL2(d, a, b) \
    asm("mul.rn.f16x2 %0, %1, %2;" : "=r"(d) : "r"(a), "r"(b))
#define SPLATH2(d, f) \
    asm("cvt.rn.f16x2.f32 %0, %1, %1;" : "=r"(d) : "f"(f))

// ---------------------------------------------------------------------------
// Prologue: W -> fp16 in mma-A fragment order.
__global__ void CIN_52553219834054_wsplit(const float* __restrict__ W1,
                                          const float* __restrict__ W2) {
    const int idx = blockIdx.x * 256 + threadIdx.x;    // 0..65535
    const int c    = idx >> 9;
    const int rem  = idx & 511;
    const int mh   = rem >> 8;
    const int rem2 = rem & 255;
    const int q    = rem2 >> 5;
    const int lane = rem2 & 31;
    const int kk = q >> 1, m = q & 1;
    const int l = c >> 6, i = c & 63;
    const float* __restrict__ W = l ? W2 : W1;
    const int r = lane >> 2, tg = lane & 3;

    uint32_t regs[4];
    #pragma unroll
    for (int e = 0; e < 4; ++e) {
        const int row = mh * 32 + m * 16 + r + (e & 1) * 8;
        const int j   = kk * 16 + tg * 2 + (e >> 1) * 8;
        const float v0 = W[row * 4096 + i * 64 + j];
        const float v1 = W[row * 4096 + i * 64 + j + 1];
        regs[e] = h2bits(__floats2half2_rn(v0, v1));   // .x = v0 (low bits)
    }
    g_Wf[idx] = make_uint4(regs[0], regs[1], regs[2], regs[3]);
}

// ---------------------------------------------------------------------------
__global__ __launch_bounds__(128, 4) void CIN_52553219834054_kernel(
    const float* __restrict__ x,
    const float* __restrict__ b1, const float* __restrict__ b2,
    const float* __restrict__ Wfc, const float* __restrict__ bfc,
    float* __restrict__ out)
{
    extern __shared__ __align__(16) char smem[];
    const uint32_t sb = s2u(smem);
    const int tid = threadIdx.x, wid = tid >> 5, lane = tid & 31;
    const int mh = wid >> 1;          // m-half (rows mh*32..+31)
    const int nh = wid & 1;           // n-half (cols nh*32..+31)

    // ---- init: x -> XS fp32; h0 = fp16(x) ----
    {
        const float4* xg = (const float4*)(x + (size_t)blockIdx.x * 4096);
        float* XSf = (float*)(smem + XS_OFF);
        char* hb = smem + HH_OFF;
        #pragma unroll
        for (int t = 0; t < 8; ++t) {
            const int q = tid + t * 128;            // 0..1023
            const int i = q >> 4, d4 = (q & 15) * 4;
            const float4 v = xg[q];
            *(float4*)(XSf + i * 68 + d4) = v;
            *(uint2*)(hb + i * 144 + d4 * 2) =
                make_uint2(h2bits(__floats2half2_rn(v.x, v.y)),
                           h2bits(__floats2half2_rn(v.z, v.w)));
        }
    }
    __syncthreads();

    // h LDSM base for this warp: + kk*2304 + g*32
    const uint32_t hbase = sb + HH_OFF + (lane & 15) * 144
                         + ((lane >> 4) << 4) + (nh * 2) * 32;
    const uint4* __restrict__ wfp = &g_Wf[mh * 256 + lane];  // + c*512 + kk*64
    // x for the B-frag scaling: lane's d values are nh*32 + np*8 + (lane>>2)
    const float* __restrict__ xcol = (const float*)(smem + XS_OFF)
                                   + nh * 32 + (lane >> 2);

    // A-fragment 4-slot ring: consume A[kk], prefetch step+3 into A[(kk+3)&3]
    uint4 A[4][2];
    {   // preload steps 0..2 (chunk 0, kk 0..2)
        A[0][0] = __ldg(wfp);       A[0][1] = __ldg(wfp + 32);
        A[1][0] = __ldg(wfp + 64);  A[1][1] = __ldg(wfp + 96);
        A[2][0] = __ldg(wfp + 128); A[2][1] = __ldg(wfp + 160);
    }

    float pool = 0.0f;

    #pragma unroll 1
    for (int l = 0; l < 2; ++l) {
        // ---- h B-fragments (fp16) into registers, once per layer ----
        uint32_t Bh[4][2][4];
        {
            #pragma unroll
            for (int kk = 0; kk < 4; ++kk)
                #pragma unroll
                for (int g = 0; g < 2; ++g)
                    LDSM4T(Bh[kk][g], hbase + kk * 2304 + g * 32);
        }
        __syncthreads();   // all B-frags read before epilogue may rewrite h

        float acc[2][4][4];

        #pragma unroll 2
        for (int i = 0; i < 64; ++i) {
            const int c = l * 64 + i;

            // x splats for this chunk: one per np (d = nh*32 + np*8 + lane>>2)
            uint32_t xs2[4];
            #pragma unroll
            for (int np = 0; np < 4; ++np)
                SPLATH2(xs2[np], xcol[i * 68 + np * 8]);

            #pragma unroll
            for (int kk = 0; kk < 4; ++kk) {
                // prefetch A-fragments 3 steps ahead (s = c*4+kk; s&3 == kk)
                {
                    const int nc  = (kk >= 1) ? c + 1 : c;
                    const int nkk = (kk + 3) & 3;
                    if (nc < 128) {
                        const uint4* p = wfp + nc * 512 + nkk * 64;
                        uint4* dst = A[(kk + 3) & 3];
                        dst[0] = __ldg(p); dst[1] = __ldg(p + 32);
                    }
                }
                // scale B-frags by x (one f16x2 mul per reg)
                uint32_t zb[4][2];
                #pragma unroll
                for (int np = 0; np < 4; ++np) {
                    const int g = np >> 1, pr = (np & 1) * 2;
                    HMUL2(zb[np][0], Bh[kk][g][pr],     xs2[np]);
                    HMUL2(zb[np][1], Bh[kk][g][pr + 1], xs2[np]);
                }
                const uint32_t* Ah[2] = { (const uint32_t*)&A[kk][0],
                                          (const uint32_t*)&A[kk][1] };
                #pragma unroll
                for (int m = 0; m < 2; ++m)
                    #pragma unroll
                    for (int np = 0; np < 4; ++np) {
                        if (i == 0 && kk == 0) {
                            MMAHZ(acc[m][np], Ah[m], zb[np][0], zb[np][1]);
                        } else {
                            MMAH (acc[m][np], Ah[m], zb[np][0], zb[np][1]);
                        }
                    }
            }
        }
        __syncthreads();   // all h reads done before epilogue rewrites h

        // ---- epilogue: bias + relu, pool, write next h (fp16) ----
        {
            const float* bg = l ? b2 : b1;
            const int d0 = nh * 32 + (lane & 3) * 2;
            char* hb = smem + HH_OFF;
            float ps = 0.0f;
            #pragma unroll
            for (int m = 0; m < 2; ++m) {
                const int o_lo = mh * 32 + m * 16 + (lane >> 2);
                const int o_hi = o_lo + 8;
                const float blv = bg[o_lo], bhv = bg[o_hi];
                const float wlv = Wfc[l * 64 + o_lo], whv = Wfc[l * 64 + o_hi];
                #pragma unroll
                for (int np = 0; np < 4; ++np) {
                    const int d = d0 + np * 8;
                    float v0 = fmaxf(acc[m][np][0] + blv, 0.0f);
                    float v1 = fmaxf(acc[m][np][1] + blv, 0.0f);
                    float v2 = fmaxf(acc[m][np][2] + bhv, 0.0f);
                    float v3 = fmaxf(acc[m][np][3] + bhv, 0.0f);
                    ps += wlv * (v0 + v1) + whv * (v2 + v3);
                    if (l == 0) {
                        *(uint32_t*)(hb + o_lo * 144 + d * 2) =
                            h2bits(__floats2half2_rn(v0, v1));
                        *(uint32_t*)(hb + o_hi * 144 + d * 2) =
                            h2bits(__floats2half2_rn(v2, v3));
                    }
                }
            }
            pool += ps;
        }
        __syncthreads();   // new h visible before next-layer Bh load
    }

    // ---- reduce pool across 4 warps, write out ----
    #pragma unroll
    for (int off = 16; off > 0; off >>= 1)
        pool += __shfl_xor_sync(0xffffffffu, pool, off);
    float* pb = (float*)(smem + POOL_OFF);
    if (lane == 0) pb[wid] = pool;
    __syncthreads();
    if (tid == 0)
        out[blockIdx.x] = pb[0] + pb[1] + pb[2] + pb[3] + bfc[0];
}

// ---------------------------------------------------------------------------
extern "C" void kernel_launch(void* const* d_in, const int* in_sizes, int n_in,
                              void* d_out, int out_size) {
    const float* x   = (const float*)d_in[0];
    const float* W1  = (const float*)d_in[1];
    const float* b1  = (const float*)d_in[2];
    const float* W2  = (const float*)d_in[3];
    const float* b2  = (const float*)d_in[4];
    const float* Wfc = (const float*)d_in[5];
    const float* bfc = (const float*)d_in[6];

    cudaFuncSetAttribute(CIN_52553219834054_kernel,
                         cudaFuncAttributeMaxDynamicSharedMemorySize, SMEM_TOTAL);

    CIN_52553219834054_wsplit<<<256, 256>>>(W1, W2);
    CIN_52553219834054_kernel<<<1024, 128, SMEM_TOTAL>>>(
        x, b1, b2, Wfc, bfc, (float*)d_out);
}